// round 6
// baseline (speedup 1.0000x reference)
#include <cuda_runtime.h>
#include <cuda_bf16.h>
#include <math.h>
#include <stdint.h>

// Problem constants
#define ORDER   32
#define WHID    1024
#define OUTDIM  4096
#define SMAX    2048

// ---------------------------------------------------------------------------
// Scratch (device globals -- no allocations allowed)
// ---------------------------------------------------------------------------
__device__ __nv_bfloat16 g_Ahi[SMAX * WHID];   // H1 hi (gemm2 input)
__device__ __nv_bfloat16 g_Alo[SMAX * WHID];   // H1 lo
__device__ __nv_bfloat16 g_Chi[SMAX * WHID];   // H2 hi (gemm3 input)
__device__ __nv_bfloat16 g_Clo[SMAX * WHID];   // H2 lo
__device__ __nv_bfloat16 g_W2hi[WHID * WHID];
__device__ __nv_bfloat16 g_W2lo[WHID * WHID];
__device__ __nv_bfloat16 g_W3hi[WHID * WHID];
__device__ __nv_bfloat16 g_W3lo[WHID * WHID];
__device__ float g_hsum[WHID];
__device__ float g_wsum[OUTDIM];
__device__ float g_bsum[1];

// ---------------------------------------------------------------------------
// PTX helpers (plain sm_80+ features only)
// ---------------------------------------------------------------------------
__device__ __forceinline__ uint32_t smem_u32(const void* p) {
    uint32_t a;
    asm("{ .reg .u64 t; cvta.to.shared.u64 t, %1; cvt.u32.u64 %0, t; }"
        : "=r"(a) : "l"(p));
    return a;
}
__device__ __forceinline__ void cp16(uint32_t saddr, const void* g) {
    asm volatile("cp.async.cg.shared.global [%0], [%1], 16;"
                 :: "r"(saddr), "l"(g) : "memory");
}
__device__ __forceinline__ void cp_commit() {
    asm volatile("cp.async.commit_group;" ::: "memory");
}
template <int N>
__device__ __forceinline__ void cp_wait() {
    asm volatile("cp.async.wait_group %0;" :: "n"(N) : "memory");
}
__device__ __forceinline__ void ldmx4(uint32_t* r, uint32_t addr) {
    asm volatile("ldmatrix.sync.aligned.m8n8.x4.shared.b16 {%0,%1,%2,%3}, [%4];"
                 : "=r"(r[0]), "=r"(r[1]), "=r"(r[2]), "=r"(r[3]) : "r"(addr));
}
__device__ __forceinline__ void mma16816(float* d, const uint32_t* a,
                                         const uint32_t* b) {
    asm volatile(
        "mma.sync.aligned.m16n8k16.row.col.f32.bf16.bf16.f32 "
        "{%0,%1,%2,%3}, {%4,%5,%6,%7}, {%8,%9}, {%0,%1,%2,%3};"
        : "+f"(d[0]), "+f"(d[1]), "+f"(d[2]), "+f"(d[3])
        : "r"(a[0]), "r"(a[1]), "r"(a[2]), "r"(a[3]), "r"(b[0]), "r"(b[1]));
}

// ---------------------------------------------------------------------------
// GELU (tanh approximation, matches jax.nn.gelu)
// ---------------------------------------------------------------------------
__device__ __forceinline__ float gelu_f(float x) {
    const float k0 = 0.7978845608028654f;
    float x3 = x * x * x;
    float t = tanhf(k0 * (x + 0.044715f * x3));
    return 0.5f * x * (1.0f + t);
}

__device__ __forceinline__ void bf16_split(float x, __nv_bfloat16& hi, __nv_bfloat16& lo) {
    hi = __float2bfloat16_rn(x);
    lo = __float2bfloat16_rn(x - __bfloat162float(hi));
}

// ---------------------------------------------------------------------------
// init: zero hsum, compute bsum
// ---------------------------------------------------------------------------
__global__ __launch_bounds__(256)
void init_kernel(const float* __restrict__ sources,
                 const float* __restrict__ Wb,
                 const float* __restrict__ bb, int S) {
    int tid = threadIdx.x;
    for (int j = tid; j < WHID; j += 256) g_hsum[j] = 0.0f;

    float wb0 = Wb[0], wb1 = Wb[1], wb2 = Wb[2], wb3 = Wb[3];
    float acc = 0.0f;
    for (int s = tid; s < S; s += 256) {
        float4 v = reinterpret_cast<const float4*>(sources)[s];
        acc += v.x * wb0 + v.y * wb1 + v.z * wb2 + v.w * wb3;
    }
    __shared__ float red[256];
    red[tid] = acc;
    __syncthreads();
    for (int o = 128; o > 0; o >>= 1) {
        if (tid < o) red[tid] += red[tid + o];
        __syncthreads();
    }
    if (tid == 0) g_bsum[0] = red[0] + (float)S * bb[0];
}

// ---------------------------------------------------------------------------
// prep_w: split W2, W3 into bf16 hi/lo
// ---------------------------------------------------------------------------
__global__ __launch_bounds__(256)
void prep_w_kernel(const float* __restrict__ W2, const float* __restrict__ W3) {
    int idx = blockIdx.x * 256 + threadIdx.x;
    const int M1 = WHID * WHID;
    if (idx < M1) {
        __nv_bfloat16 hi, lo;
        bf16_split(W2[idx], hi, lo);
        g_W2hi[idx] = hi; g_W2lo[idx] = lo;
    } else {
        int j = idx - M1;
        __nv_bfloat16 hi, lo;
        bf16_split(W3[j], hi, lo);
        g_W3hi[j] = hi; g_W3lo[j] = lo;
    }
}

// ---------------------------------------------------------------------------
// Layer 1: H1 = gelu(sources @ W1^T + b1), stored as bf16 hi/lo
// ---------------------------------------------------------------------------
__global__ __launch_bounds__(256)
void layer1_kernel(const float* __restrict__ sources,
                   const float* __restrict__ W1,
                   const float* __restrict__ b1, int S) {
    int idx = blockIdx.x * blockDim.x + threadIdx.x;
    if (idx >= S * WHID) return;
    int s = idx >> 10;
    int j = idx & (WHID - 1);
    float4 src = reinterpret_cast<const float4*>(sources)[s];
    float4 w   = reinterpret_cast<const float4*>(W1)[j];
    float acc = src.x * w.x + src.y * w.y + src.z * w.z + src.w * w.w + b1[j];
    float g = gelu_f(acc);
    __nv_bfloat16 hi, lo;
    bf16_split(g, hi, lo);
    g_Ahi[idx] = hi; g_Alo[idx] = lo;
}

// ---------------------------------------------------------------------------
// mma.sync GEMM: C = gelu(A @ B^T + bias), 2-term bf16 split (3 MMA terms).
// CTA tile 128x128, BK=16, 512 threads / 16 warps (4x4 -> 32x32 warp tiles),
// 3-stage cp.async pipeline (48KB smem), XOR-swizzled for ldmatrix.
// stage 0: out -> g_Chi/g_Clo (bf16 split)
// stage 1: out -> column sums fused: atomicAdd into g_hsum (H3 never stored)
// ---------------------------------------------------------------------------
__device__ __forceinline__ uint32_t sw32(uint32_t off) {
    return off ^ ((off >> 3) & 0x10);
}

__global__ __launch_bounds__(512, 1)
void mma_gemm(int stage, const float* __restrict__ bias) {
    // [pipe stage][tile: 0=Ahi 1=Alo 2=Bhi 3=Blo][128 rows x 32 bytes]
    __shared__ __align__(1024) char smem[3][4][4096];

    const __nv_bfloat16* Ahi = stage ? g_Chi : g_Ahi;
    const __nv_bfloat16* Alo = stage ? g_Clo : g_Alo;
    const __nv_bfloat16* Bhi = stage ? g_W3hi : g_W2hi;
    const __nv_bfloat16* Blo = stage ? g_W3lo : g_W2lo;

    const int tid = threadIdx.x;
    const int wid = tid >> 5;
    const int lane = tid & 31;
    const int bm = blockIdx.y * 128;
    const int bn = blockIdx.x * 128;
    const int wm = wid & 3;       // 0..3 -> 32-row group
    const int wn = wid >> 2;      // 0..3 -> 32-col group

    // --- loader mapping: each thread fills 1 A-chunk + 1 B-chunk per stage ---
    // flattened chunk space: [tile(4)][chunk(256)]; thread t -> chunks t, t+512
    const int sel = (tid >= 256) ? 1 : 0;     // 0: hi tiles, 1: lo tiles
    const int ch = tid & 255;
    const int lr = ch >> 1;                   // row 0..127
    const int lc = ch & 1;                    // 16B chunk 0..1
    const uint32_t loff = sw32((uint32_t)(lr * 32 + lc * 16));
    const size_t gAoff = (size_t)(bm + lr) * WHID + lc * 8;
    const size_t gBoff = (size_t)(bn + lr) * WHID + lc * 8;
    const __nv_bfloat16* srcA = (sel ? Alo : Ahi) + gAoff;
    const __nv_bfloat16* srcB = (sel ? Blo : Bhi) + gBoff;
    const int tileA = sel;          // 0 or 1
    const int tileB = 2 + sel;      // 2 or 3

    // --- ldmatrix per-lane offsets (within a 4KB tile) ---
    uint32_t offA[2], offB[2];
#pragma unroll
    for (int i = 0; i < 2; i++) {
        int row = wm * 32 + i * 16 + (lane & 15);
        offA[i] = sw32((uint32_t)(row * 32 + (lane >> 4) * 16));
    }
#pragma unroll
    for (int j = 0; j < 2; j++) {
        int row = wn * 32 + j * 16 + (lane & 15);
        offB[j] = sw32((uint32_t)(row * 32 + (lane >> 4) * 16));
    }

    float acc[2][4][4];
#pragma unroll
    for (int i = 0; i < 2; i++)
#pragma unroll
        for (int j = 0; j < 4; j++)
#pragma unroll
            for (int q = 0; q < 4; q++) acc[i][j][q] = 0.0f;

    // prologue: issue loads for kt-iter 0 and 1 (two groups in flight)
#pragma unroll
    for (int p = 0; p < 2; p++) {
        int nk = p * 16;
        cp16(smem_u32(&smem[p][tileA][0]) + loff, srcA + nk);
        cp16(smem_u32(&smem[p][tileB][0]) + loff, srcB + nk);
        cp_commit();
    }

    const int NIT = WHID / 16;   // 64
    for (int it = 0; it < NIT; it++) {
        const int st = it % 3;
        cp_wait<1>();            // group for iter `it` complete
        __syncthreads();

        // issue loads for iter it+2 (always commit to keep group count in sync)
        if (it + 2 < NIT) {
            const int ns = (it + 2) % 3;
            const int nk = (it + 2) * 16;
            cp16(smem_u32(&smem[ns][tileA][0]) + loff, srcA + nk);
            cp16(smem_u32(&smem[ns][tileB][0]) + loff, srcB + nk);
        }
        cp_commit();

#pragma unroll
        for (int split = 0; split < 3; split++) {
            const int ta = (split == 2) ? 1 : 0;
            const int tb = (split == 1) ? 3 : 2;
            uint32_t ab = smem_u32(&smem[st][ta][0]);
            uint32_t bb = smem_u32(&smem[st][tb][0]);

            uint32_t a[2][4], b[2][4];
#pragma unroll
            for (int i = 0; i < 2; i++) ldmx4(a[i], ab + offA[i]);
#pragma unroll
            for (int j = 0; j < 2; j++) ldmx4(b[j], bb + offB[j]);

#pragma unroll
            for (int i = 0; i < 2; i++) {
#pragma unroll
                for (int jj = 0; jj < 4; jj++) {
                    uint32_t breg[2] = { b[jj >> 1][jj & 1], b[jj >> 1][(jj & 1) + 2] };
                    mma16816(acc[i][jj], a[i], breg);
                }
            }
        }
    }

    // --- epilogue ---
    if (stage == 0) {
#pragma unroll
        for (int i = 0; i < 2; i++) {
            int r0 = bm + wm * 32 + i * 16 + (lane >> 2);
            int r1 = r0 + 8;
#pragma unroll
            for (int jj = 0; jj < 4; jj++) {
                int col = bn + wn * 32 + jj * 8 + (lane & 3) * 2;
                float b0 = bias[col], b1 = bias[col + 1];
                float v00 = gelu_f(acc[i][jj][0] + b0);
                float v01 = gelu_f(acc[i][jj][1] + b1);
                float v10 = gelu_f(acc[i][jj][2] + b0);
                float v11 = gelu_f(acc[i][jj][3] + b1);
                __nv_bfloat16 h0, l0, h1, l1;
                bf16_split(v00, h0, l0); bf16_split(v01, h1, l1);
                *reinterpret_cast<__nv_bfloat162*>(g_Chi + (size_t)r0 * WHID + col) =
                    __nv_bfloat162(h0, h1);
                *reinterpret_cast<__nv_bfloat162*>(g_Clo + (size_t)r0 * WHID + col) =
                    __nv_bfloat162(l0, l1);
                bf16_split(v10, h0, l0); bf16_split(v11, h1, l1);
                *reinterpret_cast<__nv_bfloat162*>(g_Chi + (size_t)r1 * WHID + col) =
                    __nv_bfloat162(h0, h1);
                *reinterpret_cast<__nv_bfloat162*>(g_Clo + (size_t)r1 * WHID + col) =
                    __nv_bfloat162(l0, l1);
            }
        }
    } else {
        // fused column sum of gelu(acc + bias): H3 never hits global memory
        float colacc[4][2];
#pragma unroll
        for (int jj = 0; jj < 4; jj++) { colacc[jj][0] = 0.0f; colacc[jj][1] = 0.0f; }

#pragma unroll
        for (int i = 0; i < 2; i++) {
#pragma unroll
            for (int jj = 0; jj < 4; jj++) {
                int col = bn + wn * 32 + jj * 8 + (lane & 3) * 2;
                float b0 = bias[col], b1 = bias[col + 1];
                colacc[jj][0] += gelu_f(acc[i][jj][0] + b0) + gelu_f(acc[i][jj][2] + b0);
                colacc[jj][1] += gelu_f(acc[i][jj][1] + b1) + gelu_f(acc[i][jj][3] + b1);
            }
        }
        // reduce across the 8 row-replica lanes (same lane&3, different lane>>2)
#pragma unroll
        for (int o = 16; o >= 4; o >>= 1) {
#pragma unroll
            for (int jj = 0; jj < 4; jj++) {
                colacc[jj][0] += __shfl_xor_sync(0xffffffffu, colacc[jj][0], o);
                colacc[jj][1] += __shfl_xor_sync(0xffffffffu, colacc[jj][1], o);
            }
        }
        if (lane < 4) {
#pragma unroll
            for (int jj = 0; jj < 4; jj++) {
                int col = bn + wn * 32 + jj * 8 + lane * 2;
                atomicAdd(&g_hsum[col],     colacc[jj][0]);
                atomicAdd(&g_hsum[col + 1], colacc[jj][1]);
            }
        }
    }
}

// ---------------------------------------------------------------------------
// wsum[k] = hsum . W4[k,:] + S*b4[k]
// ---------------------------------------------------------------------------
__global__ __launch_bounds__(256)
void wsum_kernel(const float* __restrict__ W4,
                 const float* __restrict__ b4, float Sf) {
    int k = blockIdx.x * 8 + (threadIdx.x >> 5);
    int lane = threadIdx.x & 31;
    const float* row = W4 + (size_t)k * WHID;
    float acc = 0.0f;
    for (int t = lane; t < WHID; t += 32) acc += row[t] * g_hsum[t];
#pragma unroll
    for (int o = 16; o > 0; o >>= 1) acc += __shfl_xor_sync(0xffffffffu, acc, o);
    if (lane == 0) g_wsum[k] = acc + Sf * b4[k];
}

// ---------------------------------------------------------------------------
// Fourier: out[n] = bsum + u(x)^T K v(y)
// ---------------------------------------------------------------------------
__global__ __launch_bounds__(256)
void fourier_kernel(const float* __restrict__ r, float* __restrict__ out, int N) {
    __shared__ float Ks[64 * 64];
    for (int t = threadIdx.x; t < 64 * 64; t += 256) {
        int a = t >> 6, b = t & 63;
        int i = a & 31, j = b & 31;
        int c = (a < 32) ? ((b < 32) ? 0 : 2) : ((b < 32) ? 3 : 1);
        Ks[t] = g_wsum[c * 1024 + i * 32 + j];
    }
    __syncthreads();

    int n = blockIdx.x * 256 + threadIdx.x;
    if (n >= N) return;

    float x = r[2 * n + 0];
    float y = r[2 * n + 1];
    const float w1 = 0.6283185307179586f;   // 2*pi/10

    float sx1, cx1, sy1, cy1;
    sincosf(w1 * x, &sx1, &cx1);
    sincosf(w1 * y, &sy1, &cy1);

    float v[64];
    {
        float cc = cy1, ss = sy1;
        v[0] = cc; v[32] = ss;
#pragma unroll
        for (int k = 1; k < 32; k++) {
            float cn = cc * cy1 - ss * sy1;
            float sn = ss * cy1 + cc * sy1;
            cc = cn; ss = sn;
            v[k] = cc; v[32 + k] = ss;
        }
    }

    float res = 0.0f;
    float cxa = cx1, sxa = sx1;
#pragma unroll 1
    for (int k = 0; k < 32; k++) {
        const float4* rc = (const float4*)&Ks[k * 64];
        const float4* rs = (const float4*)&Ks[(32 + k) * 64];
        float ac = 0.0f, as2 = 0.0f;
#pragma unroll
        for (int q = 0; q < 16; q++) {
            float4 kc = rc[q];
            float4 ks = rs[q];
            ac  += kc.x * v[4 * q] + kc.y * v[4 * q + 1] +
                   kc.z * v[4 * q + 2] + kc.w * v[4 * q + 3];
            as2 += ks.x * v[4 * q] + ks.y * v[4 * q + 1] +
                   ks.z * v[4 * q + 2] + ks.w * v[4 * q + 3];
        }
        res += cxa * ac + sxa * as2;
        float cn = cxa * cx1 - sxa * sx1;
        float sn = sxa * cx1 + cxa * sx1;
        cxa = cn; sxa = sn;
    }

    out[n] = g_bsum[0] + res;
}

// ---------------------------------------------------------------------------
// kernel_launch
// ---------------------------------------------------------------------------
extern "C" void kernel_launch(void* const* d_in, const int* in_sizes, int n_in,
                              void* d_out, int out_size) {
    const float* sources = (const float*)d_in[0];
    const float* r       = (const float*)d_in[1];
    const float* W1      = (const float*)d_in[2];
    const float* b1      = (const float*)d_in[3];
    const float* W2      = (const float*)d_in[4];
    const float* b2      = (const float*)d_in[5];
    const float* W3      = (const float*)d_in[6];
    const float* b3      = (const float*)d_in[7];
    const float* W4      = (const float*)d_in[8];
    const float* b4      = (const float*)d_in[9];
    const float* Wb      = (const float*)d_in[10];
    const float* bb      = (const float*)d_in[11];
    float* out = (float*)d_out;

    const int S = in_sizes[0] / 4;
    const int N = in_sizes[1] / 2;

    // 1) bsum + zero hsum
    init_kernel<<<1, 256>>>(sources, Wb, bb, S);

    // 2) weight split (W2, W3 -> bf16 hi/lo)
    prep_w_kernel<<<2 * WHID * WHID / 256, 256>>>(W2, W3);

    // 3) layer 1 -> bf16 hi/lo activations
    layer1_kernel<<<S * WHID / 256, 256>>>(sources, W1, b1, S);

    // 4) tensor-core GELU-GEMMs (layers 2 and 3; layer-3 fuses column sum)
    {
        dim3 grid(WHID / 128, S / 128);
        mma_gemm<<<grid, 512>>>(0, b2);   // H1 -> H2 (bf16 split)
        mma_gemm<<<grid, 512>>>(1, b3);   // H2 -> hsum (fused column sum)
    }

    // 5) wsum = hsum @ W4^T + S*b4
    wsum_kernel<<<OUTDIM / 8, 256>>>(W4, b4, (float)S);

    // 6) fourier expansion
    fourier_kernel<<<(N + 255) / 256, 256>>>(r, out, N);
}

// round 7
// speedup vs baseline: 1.2742x; 1.2742x over previous
#include <cuda_runtime.h>
#include <cuda_bf16.h>
#include <math.h>
#include <stdint.h>

// Problem constants
#define ORDER   32
#define WHID    1024
#define OUTDIM  4096
#define SMAX    2048

// ---------------------------------------------------------------------------
// Scratch (device globals -- no allocations allowed)
// ---------------------------------------------------------------------------
__device__ __nv_bfloat16 g_Ahi[SMAX * WHID];   // H1 (bf16, gemm2 input)
__device__ __nv_bfloat16 g_Chi[SMAX * WHID];   // H2 (bf16, gemm3 input)
__device__ __nv_bfloat16 g_W2hi[WHID * WHID];
__device__ __nv_bfloat16 g_W2lo[WHID * WHID];
__device__ __nv_bfloat16 g_W3hi[WHID * WHID];
__device__ __nv_bfloat16 g_W3lo[WHID * WHID];
__device__ float g_hsum[WHID];
__device__ float g_wsum[OUTDIM];
__device__ float g_bsum[1];

// ---------------------------------------------------------------------------
// PTX helpers (plain sm_80+ features only)
// ---------------------------------------------------------------------------
__device__ __forceinline__ uint32_t smem_u32(const void* p) {
    uint32_t a;
    asm("{ .reg .u64 t; cvta.to.shared.u64 t, %1; cvt.u32.u64 %0, t; }"
        : "=r"(a) : "l"(p));
    return a;
}
__device__ __forceinline__ void cp16(uint32_t saddr, const void* g) {
    asm volatile("cp.async.cg.shared.global [%0], [%1], 16;"
                 :: "r"(saddr), "l"(g) : "memory");
}
__device__ __forceinline__ void cp_commit() {
    asm volatile("cp.async.commit_group;" ::: "memory");
}
template <int N>
__device__ __forceinline__ void cp_wait() {
    asm volatile("cp.async.wait_group %0;" :: "n"(N) : "memory");
}
__device__ __forceinline__ void ldmx4(uint32_t* r, uint32_t addr) {
    asm volatile("ldmatrix.sync.aligned.m8n8.x4.shared.b16 {%0,%1,%2,%3}, [%4];"
                 : "=r"(r[0]), "=r"(r[1]), "=r"(r[2]), "=r"(r[3]) : "r"(addr));
}
__device__ __forceinline__ void mma16816(float* d, const uint32_t* a,
                                         const uint32_t* b) {
    asm volatile(
        "mma.sync.aligned.m16n8k16.row.col.f32.bf16.bf16.f32 "
        "{%0,%1,%2,%3}, {%4,%5,%6,%7}, {%8,%9}, {%0,%1,%2,%3};"
        : "+f"(d[0]), "+f"(d[1]), "+f"(d[2]), "+f"(d[3])
        : "r"(a[0]), "r"(a[1]), "r"(a[2]), "r"(a[3]), "r"(b[0]), "r"(b[1]));
}

// ---------------------------------------------------------------------------
// GELU (tanh approximation, matches jax.nn.gelu)
// ---------------------------------------------------------------------------
__device__ __forceinline__ float gelu_f(float x) {
    const float k0 = 0.7978845608028654f;
    float x3 = x * x * x;
    float t = tanhf(k0 * (x + 0.044715f * x3));
    return 0.5f * x * (1.0f + t);
}

__device__ __forceinline__ void bf16_split(float x, __nv_bfloat16& hi, __nv_bfloat16& lo) {
    hi = __float2bfloat16_rn(x);
    lo = __float2bfloat16_rn(x - __bfloat162float(hi));
}

// ---------------------------------------------------------------------------
// init: zero hsum, compute bsum
// ---------------------------------------------------------------------------
__global__ __launch_bounds__(256)
void init_kernel(const float* __restrict__ sources,
                 const float* __restrict__ Wb,
                 const float* __restrict__ bb, int S) {
    int tid = threadIdx.x;
    for (int j = tid; j < WHID; j += 256) g_hsum[j] = 0.0f;

    float wb0 = Wb[0], wb1 = Wb[1], wb2 = Wb[2], wb3 = Wb[3];
    float acc = 0.0f;
    for (int s = tid; s < S; s += 256) {
        float4 v = reinterpret_cast<const float4*>(sources)[s];
        acc += v.x * wb0 + v.y * wb1 + v.z * wb2 + v.w * wb3;
    }
    __shared__ float red[256];
    red[tid] = acc;
    __syncthreads();
    for (int o = 128; o > 0; o >>= 1) {
        if (tid < o) red[tid] += red[tid + o];
        __syncthreads();
    }
    if (tid == 0) g_bsum[0] = red[0] + (float)S * bb[0];
}

// ---------------------------------------------------------------------------
// prep_w: split W2, W3 into bf16 hi/lo (weights keep 2-term precision --
// weight rounding is systematic and would not average out in the column sum)
// ---------------------------------------------------------------------------
__global__ __launch_bounds__(256)
void prep_w_kernel(const float* __restrict__ W2, const float* __restrict__ W3) {
    int idx = blockIdx.x * 256 + threadIdx.x;
    const int M1 = WHID * WHID;
    if (idx < M1) {
        __nv_bfloat16 hi, lo;
        bf16_split(W2[idx], hi, lo);
        g_W2hi[idx] = hi; g_W2lo[idx] = lo;
    } else {
        int j = idx - M1;
        __nv_bfloat16 hi, lo;
        bf16_split(W3[j], hi, lo);
        g_W3hi[j] = hi; g_W3lo[j] = lo;
    }
}

// ---------------------------------------------------------------------------
// Layer 1: H1 = gelu(sources @ W1^T + b1), stored as bf16 (activation lo
// dropped: per-row random rounding error averages out in the final colsum)
// ---------------------------------------------------------------------------
__global__ __launch_bounds__(256)
void layer1_kernel(const float* __restrict__ sources,
                   const float* __restrict__ W1,
                   const float* __restrict__ b1, int S) {
    int idx = blockIdx.x * blockDim.x + threadIdx.x;
    if (idx >= S * WHID) return;
    int s = idx >> 10;
    int j = idx & (WHID - 1);
    float4 src = reinterpret_cast<const float4*>(sources)[s];
    float4 w   = reinterpret_cast<const float4*>(W1)[j];
    float acc = src.x * w.x + src.y * w.y + src.z * w.z + src.w * w.w + b1[j];
    g_Ahi[idx] = __float2bfloat16_rn(gelu_f(acc));
}

// ---------------------------------------------------------------------------
// mma.sync GEMM: C = gelu(A @ B^T + bias)
// A bf16 (single term), B split hi/lo -> 2 MMA terms: A.Bhi + A.Blo
// CTA tile 128x128, BK=16, 512 threads / 16 warps (4x4 -> 32x32 warp tiles),
// 3-stage cp.async pipeline (36KB smem), XOR-swizzled for ldmatrix.
// stage 0: out -> g_Chi (bf16)
// stage 1: out -> column sums fused: atomicAdd into g_hsum (H3 never stored)
// ---------------------------------------------------------------------------
__device__ __forceinline__ uint32_t sw32(uint32_t off) {
    return off ^ ((off >> 3) & 0x10);
}

__global__ __launch_bounds__(512, 1)
void mma_gemm(int stage, const float* __restrict__ bias) {
    // [pipe stage][tile: 0=A 1=Bhi 2=Blo][128 rows x 32 bytes]
    __shared__ __align__(1024) char smem[3][3][4096];

    const __nv_bfloat16* A   = stage ? g_Chi : g_Ahi;
    const __nv_bfloat16* Bhi = stage ? g_W3hi : g_W2hi;
    const __nv_bfloat16* Blo = stage ? g_W3lo : g_W2lo;

    const int tid = threadIdx.x;
    const int wid = tid >> 5;
    const int lane = tid & 31;
    const int bm = blockIdx.y * 128;
    const int bn = blockIdx.x * 128;
    const int wm = wid & 3;       // 0..3 -> 32-row group
    const int wn = wid >> 2;      // 0..3 -> 32-col group

    // --- loader mapping ---
    // threads 0..255  : A tile,  1 chunk each
    // threads 256..511: Bhi+Blo, 1 chunk each tile
    const int isB = (tid >= 256) ? 1 : 0;
    const int ch = tid & 255;
    const int lr = ch >> 1;                   // row 0..127
    const int lc = ch & 1;                    // 16B chunk 0..1
    const uint32_t loff = sw32((uint32_t)(lr * 32 + lc * 16));
    const size_t gAoff = (size_t)(bm + lr) * WHID + lc * 8;
    const size_t gBoff = (size_t)(bn + lr) * WHID + lc * 8;
    const __nv_bfloat16* src0 = isB ? (Bhi + gBoff) : (A + gAoff);
    const __nv_bfloat16* src1 = Blo + gBoff;      // only used when isB
    const int tile0 = isB ? 1 : 0;

    // --- ldmatrix per-lane offsets (within a 4KB tile) ---
    uint32_t offA[2], offB[2];
#pragma unroll
    for (int i = 0; i < 2; i++) {
        int row = wm * 32 + i * 16 + (lane & 15);
        offA[i] = sw32((uint32_t)(row * 32 + (lane >> 4) * 16));
    }
#pragma unroll
    for (int j = 0; j < 2; j++) {
        int row = wn * 32 + j * 16 + (lane & 15);
        offB[j] = sw32((uint32_t)(row * 32 + (lane >> 4) * 16));
    }

    float acc[2][4][4];
#pragma unroll
    for (int i = 0; i < 2; i++)
#pragma unroll
        for (int j = 0; j < 4; j++)
#pragma unroll
            for (int q = 0; q < 4; q++) acc[i][j][q] = 0.0f;

    // prologue: issue loads for kt-iter 0 and 1 (two groups in flight)
#pragma unroll
    for (int p = 0; p < 2; p++) {
        int nk = p * 16;
        cp16(smem_u32(&smem[p][tile0][0]) + loff, src0 + nk);
        if (isB) cp16(smem_u32(&smem[p][2][0]) + loff, src1 + nk);
        cp_commit();
    }

    const int NIT = WHID / 16;   // 64
    for (int it = 0; it < NIT; it++) {
        const int st = it % 3;
        cp_wait<1>();            // group for iter `it` complete
        __syncthreads();

        // issue loads for iter it+2 (always commit to keep group count in sync)
        if (it + 2 < NIT) {
            const int ns = (it + 2) % 3;
            const int nk = (it + 2) * 16;
            cp16(smem_u32(&smem[ns][tile0][0]) + loff, src0 + nk);
            if (isB) cp16(smem_u32(&smem[ns][2][0]) + loff, src1 + nk);
        }
        cp_commit();

        // load A fragments once; reuse for both B splits
        uint32_t a[2][4];
        {
            uint32_t ab = smem_u32(&smem[st][0][0]);
#pragma unroll
            for (int i = 0; i < 2; i++) ldmx4(a[i], ab + offA[i]);
        }

#pragma unroll
        for (int split = 0; split < 2; split++) {
            uint32_t bb = smem_u32(&smem[st][1 + split][0]);
            uint32_t b[2][4];
#pragma unroll
            for (int j = 0; j < 2; j++) ldmx4(b[j], bb + offB[j]);

#pragma unroll
            for (int i = 0; i < 2; i++) {
#pragma unroll
                for (int jj = 0; jj < 4; jj++) {
                    uint32_t breg[2] = { b[jj >> 1][jj & 1], b[jj >> 1][(jj & 1) + 2] };
                    mma16816(acc[i][jj], a[i], breg);
                }
            }
        }
    }

    // --- epilogue ---
    if (stage == 0) {
#pragma unroll
        for (int i = 0; i < 2; i++) {
            int r0 = bm + wm * 32 + i * 16 + (lane >> 2);
            int r1 = r0 + 8;
#pragma unroll
            for (int jj = 0; jj < 4; jj++) {
                int col = bn + wn * 32 + jj * 8 + (lane & 3) * 2;
                float b0 = bias[col], b1 = bias[col + 1];
                __nv_bfloat16 h0 = __float2bfloat16_rn(gelu_f(acc[i][jj][0] + b0));
                __nv_bfloat16 h1 = __float2bfloat16_rn(gelu_f(acc[i][jj][1] + b1));
                *reinterpret_cast<__nv_bfloat162*>(g_Chi + (size_t)r0 * WHID + col) =
                    __nv_bfloat162(h0, h1);
                h0 = __float2bfloat16_rn(gelu_f(acc[i][jj][2] + b0));
                h1 = __float2bfloat16_rn(gelu_f(acc[i][jj][3] + b1));
                *reinterpret_cast<__nv_bfloat162*>(g_Chi + (size_t)r1 * WHID + col) =
                    __nv_bfloat162(h0, h1);
            }
        }
    } else {
        // fused column sum of gelu(acc + bias): H3 never hits global memory
        float colacc[4][2];
#pragma unroll
        for (int jj = 0; jj < 4; jj++) { colacc[jj][0] = 0.0f; colacc[jj][1] = 0.0f; }

#pragma unroll
        for (int i = 0; i < 2; i++) {
#pragma unroll
            for (int jj = 0; jj < 4; jj++) {
                int col = bn + wn * 32 + jj * 8 + (lane & 3) * 2;
                float b0 = bias[col], b1 = bias[col + 1];
                colacc[jj][0] += gelu_f(acc[i][jj][0] + b0) + gelu_f(acc[i][jj][2] + b0);
                colacc[jj][1] += gelu_f(acc[i][jj][1] + b1) + gelu_f(acc[i][jj][3] + b1);
            }
        }
        // reduce across the 8 row-replica lanes (same lane&3, different lane>>2)
#pragma unroll
        for (int o = 16; o >= 4; o >>= 1) {
#pragma unroll
            for (int jj = 0; jj < 4; jj++) {
                colacc[jj][0] += __shfl_xor_sync(0xffffffffu, colacc[jj][0], o);
                colacc[jj][1] += __shfl_xor_sync(0xffffffffu, colacc[jj][1], o);
            }
        }
        if (lane < 4) {
#pragma unroll
            for (int jj = 0; jj < 4; jj++) {
                int col = bn + wn * 32 + jj * 8 + lane * 2;
                atomicAdd(&g_hsum[col],     colacc[jj][0]);
                atomicAdd(&g_hsum[col + 1], colacc[jj][1]);
            }
        }
    }
}

// ---------------------------------------------------------------------------
// wsum[k] = hsum . W4[k,:] + S*b4[k]
// ---------------------------------------------------------------------------
__global__ __launch_bounds__(256)
void wsum_kernel(const float* __restrict__ W4,
                 const float* __restrict__ b4, float Sf) {
    int k = blockIdx.x * 8 + (threadIdx.x >> 5);
    int lane = threadIdx.x & 31;
    const float* row = W4 + (size_t)k * WHID;
    float acc = 0.0f;
    for (int t = lane; t < WHID; t += 32) acc += row[t] * g_hsum[t];
#pragma unroll
    for (int o = 16; o > 0; o >>= 1) acc += __shfl_xor_sync(0xffffffffu, acc, o);
    if (lane == 0) g_wsum[k] = acc + Sf * b4[k];
}

// ---------------------------------------------------------------------------
// Fourier: out[n] = bsum + u(x)^T K v(y)
// ---------------------------------------------------------------------------
__global__ __launch_bounds__(256)
void fourier_kernel(const float* __restrict__ r, float* __restrict__ out, int N) {
    __shared__ float Ks[64 * 64];
    for (int t = threadIdx.x; t < 64 * 64; t += 256) {
        int a = t >> 6, b = t & 63;
        int i = a & 31, j = b & 31;
        int c = (a < 32) ? ((b < 32) ? 0 : 2) : ((b < 32) ? 3 : 1);
        Ks[t] = g_wsum[c * 1024 + i * 32 + j];
    }
    __syncthreads();

    int n = blockIdx.x * 256 + threadIdx.x;
    if (n >= N) return;

    float x = r[2 * n + 0];
    float y = r[2 * n + 1];
    const float w1 = 0.6283185307179586f;   // 2*pi/10

    float sx1, cx1, sy1, cy1;
    sincosf(w1 * x, &sx1, &cx1);
    sincosf(w1 * y, &sy1, &cy1);

    float v[64];
    {
        float cc = cy1, ss = sy1;
        v[0] = cc; v[32] = ss;
#pragma unroll
        for (int k = 1; k < 32; k++) {
            float cn = cc * cy1 - ss * sy1;
            float sn = ss * cy1 + cc * sy1;
            cc = cn; ss = sn;
            v[k] = cc; v[32 + k] = ss;
        }
    }

    float res = 0.0f;
    float cxa = cx1, sxa = sx1;
#pragma unroll 1
    for (int k = 0; k < 32; k++) {
        const float4* rc = (const float4*)&Ks[k * 64];
        const float4* rs = (const float4*)&Ks[(32 + k) * 64];
        float ac = 0.0f, as2 = 0.0f;
#pragma unroll
        for (int q = 0; q < 16; q++) {
            float4 kc = rc[q];
            float4 ks = rs[q];
            ac  += kc.x * v[4 * q] + kc.y * v[4 * q + 1] +
                   kc.z * v[4 * q + 2] + kc.w * v[4 * q + 3];
            as2 += ks.x * v[4 * q] + ks.y * v[4 * q + 1] +
                   ks.z * v[4 * q + 2] + ks.w * v[4 * q + 3];
        }
        res += cxa * ac + sxa * as2;
        float cn = cxa * cx1 - sxa * sx1;
        float sn = sxa * cx1 + cxa * sx1;
        cxa = cn; sxa = sn;
    }

    out[n] = g_bsum[0] + res;
}

// ---------------------------------------------------------------------------
// kernel_launch
// ---------------------------------------------------------------------------
extern "C" void kernel_launch(void* const* d_in, const int* in_sizes, int n_in,
                              void* d_out, int out_size) {
    const float* sources = (const float*)d_in[0];
    const float* r       = (const float*)d_in[1];
    const float* W1      = (const float*)d_in[2];
    const float* b1      = (const float*)d_in[3];
    const float* W2      = (const float*)d_in[4];
    const float* b2      = (const float*)d_in[5];
    const float* W3      = (const float*)d_in[6];
    const float* b3      = (const float*)d_in[7];
    const float* W4      = (const float*)d_in[8];
    const float* b4      = (const float*)d_in[9];
    const float* Wb      = (const float*)d_in[10];
    const float* bb      = (const float*)d_in[11];
    float* out = (float*)d_out;

    const int S = in_sizes[0] / 4;
    const int N = in_sizes[1] / 2;

    // 1) bsum + zero hsum
    init_kernel<<<1, 256>>>(sources, Wb, bb, S);

    // 2) weight split (W2, W3 -> bf16 hi/lo)
    prep_w_kernel<<<2 * WHID * WHID / 256, 256>>>(W2, W3);

    // 3) layer 1 -> bf16 activations
    layer1_kernel<<<S * WHID / 256, 256>>>(sources, W1, b1, S);

    // 4) tensor-core GELU-GEMMs (layers 2 and 3; layer-3 fuses column sum)
    {
        dim3 grid(WHID / 128, S / 128);
        mma_gemm<<<grid, 512>>>(0, b2);   // H1 -> H2 (bf16)
        mma_gemm<<<grid, 512>>>(1, b3);   // H2 -> hsum (fused column sum)
    }

    // 5) wsum = hsum @ W4^T + S*b4
    wsum_kernel<<<OUTDIM / 8, 256>>>(W4, b4, (float)S);

    // 6) fourier expansion
    fourier_kernel<<<(N + 255) / 256, 256>>>(r, out, N);
}